// round 15
// baseline (speedup 1.0000x reference)
#include <cuda_runtime.h>
#include <cstdint>

// DilatedMask: out = float32( 33x33 sliding max of (x==0) ), separable, binary.
// Single fused kernel, one wave:
//   phase A: each block ballot-bitpacks one 16-row stripe -> g_pack (4 MB, L2)
//   phase B: dependency counters (stripe +-1); the block that completes a
//            stripe's last dependency dilates it (33-row OR + horizontal
//            +-16-bit shift/OR + evict_last float4 stores).

#define B_   8
#define H_   2048
#define W_   2048
#define R_   16
#define WPR  64                        // 32-bit words per image row
#define NW   (B_ * H_ * WPR)
#define TRB  16                        // rows per stripe
#define NS   (H_ / TRB)                // 128 stripes per batch
#define HRB  (TRB + 2 * R_)            // 48 halo rows
#define SBW  66                        // padded row stride for dilated smem

__device__ uint32_t g_pack[NW];        // 4 MB packed bits
__device__ unsigned g_cnt[B_ * NS];    // dependency counters (never reset:
                                       // +3 per replay, trigger old%3==2)

// Horizontal dilation of `mid` by +-16 bits; lo = word at lower x, hi = higher x.
__device__ __forceinline__ uint32_t hdil(uint32_t lo, uint32_t mid, uint32_t hi)
{
    const uint64_t a = ((uint64_t)mid << 32) | lo;
    uint64_t u = a | (a << 1);
    u |= u << 2;  u |= u << 4;  u |= u << 8;        // offsets 0..15
    u |= a << 16;                                   // offset 16

    const uint64_t bcat = ((uint64_t)hi << 32) | mid;
    uint64_t d = bcat | (bcat >> 1);
    d |= d >> 2;  d |= d >> 4;  d |= d >> 8;
    d |= bcat >> 16;

    return (uint32_t)(u >> 32) | (uint32_t)d;
}

// float4 store with L2 evict_last policy (output stays L2-resident across replays)
__device__ __forceinline__ void st_el(float4* p, float4 v, uint64_t pol)
{
    asm volatile(
        "st.global.L2::cache_hint.v4.f32 [%0], {%1, %2, %3, %4}, %5;"
        :: "l"(p), "f"(v.x), "f"(v.y), "f"(v.z), "f"(v.w), "l"(pol)
        : "memory");
}

__global__ __launch_bounds__(256) void fused_kernel(
    const float* __restrict__ x, float* __restrict__ out)
{
    __shared__ uint32_t sA[HRB * WPR];   // packed halo rows   (12 KB)
    __shared__ uint32_t sB[TRB * SBW];   // vert-dilated rows  (4.2 KB)
    __shared__ int sTrig[4];             // [0]=count, [1..3]=stripe ids

    const int s    = blockIdx.x;         // stripe 0..127
    const int b    = blockIdx.y;         // batch 0..7
    const int tid  = threadIdx.x;
    const int lane = tid & 31;
    const int warp = tid >> 5;

    // ================= Phase A: pack stripe (b, s) =================
    // 1024 words; each warp packs 128 words (2 rows) via 16 x 8-word ballots.
    const uint32_t wordbase = (uint32_t)(b * H_ + s * TRB) * WPR + warp * 128;
    for (int it = 0; it < 16; ++it) {
        const uint32_t w0 = wordbase + it * 8;
        float v[8];
        #pragma unroll
        for (int j = 0; j < 8; ++j)
            v[j] = __ldcs(x + ((size_t)(w0 + j) << 5) + lane);  // 128B coalesced

        uint32_t bits[8];
        #pragma unroll
        for (int j = 0; j < 8; ++j)
            bits[j] = __ballot_sync(0xffffffffu, v[j] == 0.0f);

        uint32_t myb = bits[0];
        #pragma unroll
        for (int j = 1; j < 8; ++j)
            if (lane == j) myb = bits[j];
        if (lane < 8) g_pack[w0 + lane] = myb;
    }

    __threadfence();                     // publish pack writes at gpu scope
    __syncthreads();

    // ============ Phase B trigger: bump the 3 dependent stripes ============
    if (tid == 0) {
        int n = 0;
        #pragma unroll
        for (int d = -1; d <= 1; ++d) {
            const int t = min(max(s + d, 0), NS - 1);   // edges double-bump self
            const unsigned old = atomicAdd(&g_cnt[b * NS + t], 1u);
            if (old % 3u == 2u) sTrig[1 + (n++)] = t;   // last dependency: ours
        }
        sTrig[0] = n;
        __threadfence();                 // acquire-ish: order counter obs / loads
    }
    __syncthreads();

    const int nT = sTrig[0];

    // ================= Phase B: dilate each triggered stripe =================
    uint64_t pol;
    asm("createpolicy.fractional.L2::evict_last.b64 %0, 1.0;" : "=l"(pol));
    const float4 ones = make_float4(1.0f, 1.0f, 1.0f, 1.0f);
    const int j     = tid & 63;
    const int jbase = j - lane;
    const uint32_t* in = g_pack + (size_t)b * H_ * WPR;

    for (int q = 0; q < nT; ++q) {
        const int y0 = sTrig[1 + q] * TRB;

        // halo rows [y0-16, y0+32), zero outside image; L2-coherent loads
        for (int t = tid; t < HRB * WPR; t += 256) {
            const int row = t >> 6;
            const int w   = t & 63;
            const int y   = y0 - R_ + row;
            const int yc  = min(max(y, 0), H_ - 1);
            uint32_t v = __ldcg(in + (size_t)yc * WPR + w);
            if ((unsigned)y >= (unsigned)H_) v = 0u;
            sA[t] = v;
        }
        __syncthreads();

        // vertical OR over 33 rows
        for (int t = tid; t < TRB * WPR; t += 256) {
            const int r = t >> 6;
            const int w = t & 63;
            uint32_t acc = 0u;
            #pragma unroll
            for (int d = 0; d <= 2 * R_; ++d)
                acc |= sA[t + d * WPR];
            sB[r * SBW + 1 + w] = acc;
        }
        for (int r = tid; r < TRB; r += 256) {
            sB[r * SBW]      = 0u;
            sB[r * SBW + 65] = 0u;
        }
        __syncthreads();

        // horizontal dilation + expand; warp-coalesced evict_last stores
        for (int t = tid; t < TRB * WPR; t += 256) {
            const int r = t >> 6;
            const uint32_t* row = &sB[r * SBW + j];
            const uint32_t rb = hdil(row[0], row[1], row[2]);

            float4* base = (float4*)(out + ((size_t)(b * H_ + y0 + r)) * W_)
                           + (size_t)jbase * 8;

            if (__all_sync(0xffffffffu, rb == 0xffffffffu)) {   // dominant path
                #pragma unroll
                for (int g = 0; g < 8; ++g)
                    st_el(base + g * 32 + lane, ones, pol);
            } else {
                #pragma unroll
                for (int g = 0; g < 8; ++g) {
                    const uint32_t rbg = __shfl_sync(0xffffffffu, rb,
                                                     4 * g + (lane >> 3));
                    const uint32_t nib = (rbg >> (4 * (lane & 7))) & 0xFu;
                    st_el(base + g * 32 + lane,
                          make_float4((float)(nib & 1u), (float)((nib >> 1) & 1u),
                                      (float)((nib >> 2) & 1u),
                                      (float)((nib >> 3) & 1u)),
                          pol);
                }
            }
        }
        __syncthreads();                 // sB stable before next iter's reuse
    }
}

// ---------------------------------------------------------------------------
extern "C" void kernel_launch(void* const* d_in, const int* in_sizes, int n_in,
                              void* d_out, int out_size)
{
    const float* x = (const float*)d_in[0];
    float* out = (float*)d_out;

    dim3 grid(NS, B_, 1);                // (128, 8) = 1024 blocks, one wave
    fused_kernel<<<grid, 256>>>(x, out);
}